// round 2
// baseline (speedup 1.0000x reference)
#include <cuda_runtime.h>

#define NN 50000
#define EE 1600000
#define DD 128
#define GG 512

// ---------------- scratch (static device globals; no allocation) ----------------
__device__ float g_agg[NN * DD];     // aggregation buffer (re-zeroed per layer)
__device__ float g_x1[NN * DD];      // layer output ping
__device__ float g_x2[NN * DD];      // layer output pong
__device__ float g_invdeg[NN];       // deg accumulator, then 1/max(deg,1)
__device__ int   g_src[EE];
__device__ int   g_dst[EE];
__device__ int   g_batch[NN];
__device__ float g_acc[GG];          // pooled dot accumulator
__device__ float g_cnt[GG];          // nodes per graph
__device__ int   g_is64;             // 1 if integer inputs are int64, 0 if int32

// ---------------- dtype probe: int64 vs int32 edge/batch arrays ----------------
__global__ void detect_dtype_kernel(const void* __restrict__ ei) {
    const long long* p = (const long long*)ei;
    int ok = 1;
#pragma unroll 1
    for (int i = 0; i < 64; i++) {
        long long v = p[i];
        if (v < 0 || v >= NN) ok = 0;
    }
    g_is64 = ok;
}

// ---------------- small init kernels ----------------
__global__ void zero_agg_kernel() {
    float4 z = make_float4(0.f, 0.f, 0.f, 0.f);
    int n = NN * DD / 4;
    for (int i = blockIdx.x * blockDim.x + threadIdx.x; i < n; i += gridDim.x * blockDim.x)
        ((float4*)g_agg)[i] = z;
}

__global__ void zero_small_kernel() {
    int i = blockIdx.x * blockDim.x + threadIdx.x;
    if (i < NN) g_invdeg[i] = 0.f;
    if (i < GG) { g_acc[i] = 0.f; g_cnt[i] = 0.f; }
}

__global__ void convert_edges_kernel(const void* __restrict__ ei) {
    const int is64 = g_is64;
    const long long* p64 = (const long long*)ei;
    const int*       p32 = (const int*)ei;
    for (int i = blockIdx.x * blockDim.x + threadIdx.x; i < EE; i += gridDim.x * blockDim.x) {
        if (is64) {
            g_src[i] = (int)p64[i];
            g_dst[i] = (int)p64[EE + i];
        } else {
            g_src[i] = p32[i];
            g_dst[i] = p32[EE + i];
        }
    }
}

__global__ void convert_batch_kernel(const void* __restrict__ b) {
    const int is64 = g_is64;
    const long long* p64 = (const long long*)b;
    const int*       p32 = (const int*)b;
    for (int i = blockIdx.x * blockDim.x + threadIdx.x; i < NN; i += gridDim.x * blockDim.x) {
        int g = is64 ? (int)p64[i] : p32[i];
        g_batch[i] = g;
        atomicAdd(&g_cnt[g], 1.f);
    }
}

__global__ void deg_kernel() {
    for (int i = blockIdx.x * blockDim.x + threadIdx.x; i < EE; i += gridDim.x * blockDim.x)
        atomicAdd(&g_invdeg[g_dst[i]], 1.f);
}

__global__ void invdeg_finalize_kernel() {
    int i = blockIdx.x * blockDim.x + threadIdx.x;
    if (i < NN) g_invdeg[i] = 1.f / fmaxf(g_invdeg[i], 1.f);
}

// ---------------- edge scatter: one warp per edge, red.v4.f32 ----------------
// xsel: 0 = external x, 1 = g_x1, 2 = g_x2
__global__ void scatter_kernel(const float* __restrict__ xext, int xsel) {
    const float* xin = (xsel == 0) ? xext : (xsel == 1 ? g_x1 : g_x2);
    long long t = (long long)blockIdx.x * blockDim.x + threadIdx.x;
    int e = (int)(t >> 5);
    if (e >= EE) return;
    int lane = threadIdx.x & 31;
    int s = g_src[e];
    int d = g_dst[e];
    float4 v = ((const float4*)xin)[(size_t)s * 32 + lane];
    float* p = g_agg + (size_t)d * DD + lane * 4;
    asm volatile("red.global.add.v4.f32 [%0], {%1,%2,%3,%4};"
                 :: "l"(p), "f"(v.x), "f"(v.y), "f"(v.z), "f"(v.w) : "memory");
}

// ---------------- fused SAGE combine: Y = relu([agg*invdeg | x] @ [Wl;Wr]^T + b) ----------------
// Tiled SGEMM: BM=128, BN=128(=D), BK=16, 8x8 register tile, 256 threads.
__global__ __launch_bounds__(256) void combine_kernel(
    const float* __restrict__ xext, int xsel, int osel,
    const float* __restrict__ Wl, const float* __restrict__ bias,
    const float* __restrict__ Wr)
{
    const float* xin = (xsel == 0) ? xext : (xsel == 1 ? g_x1 : g_x2);
    float* y = (osel == 1) ? g_x1 : g_x2;

    __shared__ float As[16][132];
    __shared__ float Bs[16][132];

    const int tid  = threadIdx.x;
    const int row0 = blockIdx.x * 128;
    const int tx = tid & 15;          // col group (8 cols each)
    const int ty = tid >> 4;          // row group (8 rows each)
    const int lm = tid >> 2;          // loader row 0..63
    const int lk = (tid & 3) * 4;     // loader k offset 0,4,8,12

    float acc[8][8];
#pragma unroll
    for (int i = 0; i < 8; i++)
#pragma unroll
        for (int j = 0; j < 8; j++) acc[i][j] = 0.f;

#pragma unroll 1
    for (int kc = 0; kc < 16; kc++) {
        const int k0 = kc * 16;
        const bool from_x = (k0 >= 128);
        const int kb = from_x ? (k0 - 128) : k0;
        const float* Asrc = from_x ? xin : g_agg;
        const float* Bsrc = from_x ? Wr : Wl;

#pragma unroll
        for (int h = 0; h < 2; h++) {
            int m = lm + h * 64;
            int gr = row0 + m;
            float4 v = make_float4(0.f, 0.f, 0.f, 0.f);
            if (gr < NN) {
                v = *(const float4*)(Asrc + (size_t)gr * DD + kb + lk);
                if (!from_x) {
                    float s = g_invdeg[gr];
                    v.x *= s; v.y *= s; v.z *= s; v.w *= s;
                }
            }
            As[lk + 0][m] = v.x; As[lk + 1][m] = v.y;
            As[lk + 2][m] = v.z; As[lk + 3][m] = v.w;

            // B tile: output col j = m (0..127)
            float4 w = *(const float4*)(Bsrc + (size_t)m * DD + kb + lk);
            Bs[lk + 0][m] = w.x; Bs[lk + 1][m] = w.y;
            Bs[lk + 2][m] = w.z; Bs[lk + 3][m] = w.w;
        }
        __syncthreads();

#pragma unroll
        for (int k = 0; k < 16; k++) {
            float4 a0 = *(const float4*)&As[k][ty * 8];
            float4 a1 = *(const float4*)&As[k][ty * 8 + 4];
            float4 b0 = *(const float4*)&Bs[k][tx * 8];
            float4 b1 = *(const float4*)&Bs[k][tx * 8 + 4];
            float a[8] = {a0.x, a0.y, a0.z, a0.w, a1.x, a1.y, a1.z, a1.w};
            float bb[8] = {b0.x, b0.y, b0.z, b0.w, b1.x, b1.y, b1.z, b1.w};
#pragma unroll
            for (int i = 0; i < 8; i++)
#pragma unroll
                for (int j = 0; j < 8; j++)
                    acc[i][j] += a[i] * bb[j];
        }
        __syncthreads();
    }

#pragma unroll
    for (int i = 0; i < 8; i++) {
        int gr = row0 + ty * 8 + i;
        if (gr >= NN) continue;
#pragma unroll
        for (int j = 0; j < 8; j++) {
            int c = tx * 8 + j;
            float v = acc[i][j] + bias[c];
            y[(size_t)gr * DD + c] = fmaxf(v, 0.f);
        }
    }
}

// ---------------- pooling: warp per node, dot with fc_w, atomic per graph ----------------
__global__ void pool_kernel(const float* __restrict__ fcw) {
    long long t = (long long)blockIdx.x * blockDim.x + threadIdx.x;
    int n = (int)(t >> 5);
    if (n >= NN) return;
    int lane = threadIdx.x & 31;
    float4 xv = ((const float4*)g_x1)[(size_t)n * 32 + lane];
    float4 wv = ((const float4*)fcw)[lane];
    float d = xv.x * wv.x + xv.y * wv.y + xv.z * wv.z + xv.w * wv.w;
#pragma unroll
    for (int o = 16; o; o >>= 1) d += __shfl_xor_sync(0xffffffffu, d, o);
    if (lane == 0) atomicAdd(&g_acc[g_batch[n]], d);
}

__global__ void final_kernel(float* __restrict__ out, const float* __restrict__ fcb) {
    int g = blockIdx.x * blockDim.x + threadIdx.x;
    if (g < GG) out[g] = g_acc[g] / fmaxf(g_cnt[g], 1.f) + fcb[0];
}

// ---------------- launch ----------------
extern "C" void kernel_launch(void* const* d_in, const int* in_sizes, int n_in,
                              void* d_out, int out_size) {
    const float* x     = (const float*)d_in[0];
    const void*  ei    = d_in[1];
    const void*  batch = d_in[2];
    const float* Wl[3] = {(const float*)d_in[3], (const float*)d_in[6], (const float*)d_in[9]};
    const float* bb[3] = {(const float*)d_in[4], (const float*)d_in[7], (const float*)d_in[10]};
    const float* Wr[3] = {(const float*)d_in[5], (const float*)d_in[8], (const float*)d_in[11]};
    const float* fcw = (const float*)d_in[12];
    const float* fcb = (const float*)d_in[13];
    float* out = (float*)d_out;

    // one-time-per-launch prep
    detect_dtype_kernel<<<1, 1>>>(ei);
    zero_small_kernel<<<(NN + 255) / 256, 256>>>();
    convert_edges_kernel<<<4096, 256>>>(ei);
    convert_batch_kernel<<<(NN + 255) / 256, 256>>>(batch);
    deg_kernel<<<4096, 256>>>();
    invdeg_finalize_kernel<<<(NN + 255) / 256, 256>>>();

    const int scatter_blocks = (int)(((long long)EE * 32 + 255) / 256);
    const int combine_blocks = (NN + 127) / 128;

    // layer 0: x -> g_x1
    zero_agg_kernel<<<2048, 256>>>();
    scatter_kernel<<<scatter_blocks, 256>>>(x, 0);
    combine_kernel<<<combine_blocks, 256>>>(x, 0, 1, Wl[0], bb[0], Wr[0]);

    // layer 1: g_x1 -> g_x2
    zero_agg_kernel<<<2048, 256>>>();
    scatter_kernel<<<scatter_blocks, 256>>>(x, 1);
    combine_kernel<<<combine_blocks, 256>>>(x, 1, 2, Wl[1], bb[1], Wr[1]);

    // layer 2: g_x2 -> g_x1
    zero_agg_kernel<<<2048, 256>>>();
    scatter_kernel<<<scatter_blocks, 256>>>(x, 2);
    combine_kernel<<<combine_blocks, 256>>>(x, 2, 1, Wl[2], bb[2], Wr[2]);

    // pool + fc
    pool_kernel<<<(int)(((long long)NN * 32 + 255) / 256), 256>>>(fcw);
    final_kernel<<<(GG + 255) / 256, 256>>>(out, fcb);
}

// round 3
// speedup vs baseline: 1.6830x; 1.6830x over previous
#include <cuda_runtime.h>

#define NN 50000
#define EE 1600000
#define DD 128
#define GG 512
#define NB 196          // ceil(NN/256)

// ---------------- scratch (static device globals; no allocation) ----------------
__device__ float g_agg[NN * DD];     // mean-aggregated features
__device__ float g_x1[NN * DD];      // layer output ping
__device__ float g_x2[NN * DD];      // layer output pong
__device__ float g_invdeg[NN];
__device__ int   g_deg[NN];
__device__ int   g_rowptr[NN];       // exclusive prefix of deg
__device__ int   g_cursor[NN];       // placement cursors
__device__ int   g_src[EE];
__device__ int   g_dst[EE];
__device__ int   g_esrc[EE];         // src ids sorted by dst (CSR adjacency)
__device__ int   g_batch[NN];
__device__ float g_acc[GG];
__device__ float g_cnt[GG];
__device__ int   g_blocksum[NB];
__device__ int   g_blockoff[NB];
__device__ int   g_is64;

// ---------------- dtype probe: int64 vs int32 edge/batch arrays ----------------
__global__ void detect_dtype_kernel(const void* __restrict__ ei) {
    const long long* p = (const long long*)ei;
    int ok = 1;
#pragma unroll 1
    for (int i = 0; i < 64; i++) {
        long long v = p[i];
        if (v < 0 || v >= NN) ok = 0;
    }
    g_is64 = ok;
}

// ---------------- init / conversion ----------------
__global__ void zero_small_kernel() {
    int i = blockIdx.x * blockDim.x + threadIdx.x;
    if (i < NN) g_deg[i] = 0;
    if (i < GG) { g_acc[i] = 0.f; g_cnt[i] = 0.f; }
}

__global__ void convert_edges_kernel(const void* __restrict__ ei) {
    const int is64 = g_is64;
    const long long* p64 = (const long long*)ei;
    const int*       p32 = (const int*)ei;
    for (int i = blockIdx.x * blockDim.x + threadIdx.x; i < EE; i += gridDim.x * blockDim.x) {
        int s, d;
        if (is64) { s = (int)p64[i]; d = (int)p64[EE + i]; }
        else      { s = p32[i];      d = p32[EE + i]; }
        g_src[i] = s;
        g_dst[i] = d;
        atomicAdd(&g_deg[d], 1);
    }
}

__global__ void convert_batch_kernel(const void* __restrict__ b) {
    const int is64 = g_is64;
    const long long* p64 = (const long long*)b;
    const int*       p32 = (const int*)b;
    for (int i = blockIdx.x * blockDim.x + threadIdx.x; i < NN; i += gridDim.x * blockDim.x) {
        int g = is64 ? (int)p64[i] : p32[i];
        g_batch[i] = g;
        atomicAdd(&g_cnt[g], 1.f);
    }
}

// ---------------- 3-kernel exclusive scan of g_deg -> g_rowptr ----------------
__global__ void scan_part1_kernel() {          // per-block sums
    __shared__ int sh[256];
    int i = blockIdx.x * 256 + threadIdx.x;
    int v = (i < NN) ? g_deg[i] : 0;
    sh[threadIdx.x] = v;
    __syncthreads();
    for (int o = 128; o; o >>= 1) {
        if (threadIdx.x < o) sh[threadIdx.x] += sh[threadIdx.x + o];
        __syncthreads();
    }
    if (threadIdx.x == 0) g_blocksum[blockIdx.x] = sh[0];
}

__global__ void scan_part2_kernel() {          // exclusive scan of block sums (1 block)
    __shared__ int sh[256];
    int t = threadIdx.x;
    sh[t] = (t < NB) ? g_blocksum[t] : 0;
    __syncthreads();
    // Hillis-Steele inclusive scan
    for (int o = 1; o < 256; o <<= 1) {
        int v = (t >= o) ? sh[t - o] : 0;
        __syncthreads();
        sh[t] += v;
        __syncthreads();
    }
    if (t < NB) g_blockoff[t] = (t == 0) ? 0 : sh[t - 1];
}

__global__ void scan_part3_kernel() {          // in-block exclusive scan + offset
    __shared__ int sh[256];
    int t = threadIdx.x;
    int i = blockIdx.x * 256 + t;
    int v = (i < NN) ? g_deg[i] : 0;
    sh[t] = v;
    __syncthreads();
    for (int o = 1; o < 256; o <<= 1) {
        int u = (t >= o) ? sh[t - o] : 0;
        __syncthreads();
        sh[t] += u;
        __syncthreads();
    }
    if (i < NN) {
        int excl = sh[t] - v + g_blockoff[blockIdx.x];
        g_rowptr[i] = excl;
        g_cursor[i] = excl;
        g_invdeg[i] = 1.f / fmaxf((float)v, 1.f);
    }
}

__global__ void place_edges_kernel() {
    for (int i = blockIdx.x * blockDim.x + threadIdx.x; i < EE; i += gridDim.x * blockDim.x) {
        int d = g_dst[i];
        int pos = atomicAdd(&g_cursor[d], 1);
        g_esrc[pos] = g_src[i];
    }
}

// ---------------- gather mean: one warp per node, accumulate in registers ----------------
// xsel: 0 = external x, 1 = g_x1, 2 = g_x2
__global__ __launch_bounds__(256) void gather_kernel(const float* __restrict__ xext, int xsel) {
    const float* __restrict__ xin = (xsel == 0) ? xext : (xsel == 1 ? g_x1 : g_x2);
    int warp = (blockIdx.x * 256 + threadIdx.x) >> 5;
    if (warp >= NN) return;
    int lane = threadIdx.x & 31;
    int beg = g_rowptr[warp];
    int end = beg + g_deg[warp];

    float4 acc = make_float4(0.f, 0.f, 0.f, 0.f);
    int e = beg;
#pragma unroll 1
    for (; e + 4 <= end; e += 4) {
        int s0 = g_esrc[e + 0];
        int s1 = g_esrc[e + 1];
        int s2 = g_esrc[e + 2];
        int s3 = g_esrc[e + 3];
        float4 v0 = __ldg((const float4*)xin + (size_t)s0 * 32 + lane);
        float4 v1 = __ldg((const float4*)xin + (size_t)s1 * 32 + lane);
        float4 v2 = __ldg((const float4*)xin + (size_t)s2 * 32 + lane);
        float4 v3 = __ldg((const float4*)xin + (size_t)s3 * 32 + lane);
        acc.x += v0.x + v1.x + v2.x + v3.x;
        acc.y += v0.y + v1.y + v2.y + v3.y;
        acc.z += v0.z + v1.z + v2.z + v3.z;
        acc.w += v0.w + v1.w + v2.w + v3.w;
    }
#pragma unroll 1
    for (; e < end; e++) {
        int s = g_esrc[e];
        float4 v = __ldg((const float4*)xin + (size_t)s * 32 + lane);
        acc.x += v.x; acc.y += v.y; acc.z += v.z; acc.w += v.w;
    }
    float inv = g_invdeg[warp];
    acc.x *= inv; acc.y *= inv; acc.z *= inv; acc.w *= inv;
    ((float4*)g_agg)[(size_t)warp * 32 + lane] = acc;
}

// ---------------- fused SAGE combine: Y = relu([agg | x] @ [Wl;Wr]^T + b) ----------------
__global__ __launch_bounds__(256) void combine_kernel(
    const float* __restrict__ xext, int xsel, int osel,
    const float* __restrict__ Wl, const float* __restrict__ bias,
    const float* __restrict__ Wr)
{
    const float* xin = (xsel == 0) ? xext : (xsel == 1 ? g_x1 : g_x2);
    float* y = (osel == 1) ? g_x1 : g_x2;

    __shared__ float As[16][132];
    __shared__ float Bs[16][132];

    const int tid  = threadIdx.x;
    const int row0 = blockIdx.x * 128;
    const int tx = tid & 15;
    const int ty = tid >> 4;
    const int lm = tid >> 2;
    const int lk = (tid & 3) * 4;

    float acc[8][8];
#pragma unroll
    for (int i = 0; i < 8; i++)
#pragma unroll
        for (int j = 0; j < 8; j++) acc[i][j] = 0.f;

#pragma unroll 1
    for (int kc = 0; kc < 16; kc++) {
        const int k0 = kc * 16;
        const bool from_x = (k0 >= 128);
        const int kb = from_x ? (k0 - 128) : k0;
        const float* Asrc = from_x ? xin : g_agg;
        const float* Bsrc = from_x ? Wr : Wl;

#pragma unroll
        for (int h = 0; h < 2; h++) {
            int m = lm + h * 64;
            int gr = row0 + m;
            float4 v = make_float4(0.f, 0.f, 0.f, 0.f);
            if (gr < NN)
                v = *(const float4*)(Asrc + (size_t)gr * DD + kb + lk);
            As[lk + 0][m] = v.x; As[lk + 1][m] = v.y;
            As[lk + 2][m] = v.z; As[lk + 3][m] = v.w;

            float4 w = *(const float4*)(Bsrc + (size_t)m * DD + kb + lk);
            Bs[lk + 0][m] = w.x; Bs[lk + 1][m] = w.y;
            Bs[lk + 2][m] = w.z; Bs[lk + 3][m] = w.w;
        }
        __syncthreads();

#pragma unroll
        for (int k = 0; k < 16; k++) {
            float4 a0 = *(const float4*)&As[k][ty * 8];
            float4 a1 = *(const float4*)&As[k][ty * 8 + 4];
            float4 b0 = *(const float4*)&Bs[k][tx * 8];
            float4 b1 = *(const float4*)&Bs[k][tx * 8 + 4];
            float a[8] = {a0.x, a0.y, a0.z, a0.w, a1.x, a1.y, a1.z, a1.w};
            float bb[8] = {b0.x, b0.y, b0.z, b0.w, b1.x, b1.y, b1.z, b1.w};
#pragma unroll
            for (int i = 0; i < 8; i++)
#pragma unroll
                for (int j = 0; j < 8; j++)
                    acc[i][j] += a[i] * bb[j];
        }
        __syncthreads();
    }

#pragma unroll
    for (int i = 0; i < 8; i++) {
        int gr = row0 + ty * 8 + i;
        if (gr >= NN) continue;
#pragma unroll
        for (int j = 0; j < 8; j++) {
            int c = tx * 8 + j;
            float v = acc[i][j] + bias[c];
            y[(size_t)gr * DD + c] = fmaxf(v, 0.f);
        }
    }
}

// ---------------- pooling ----------------
__global__ void pool_kernel(const float* __restrict__ fcw) {
    long long t = (long long)blockIdx.x * blockDim.x + threadIdx.x;
    int n = (int)(t >> 5);
    if (n >= NN) return;
    int lane = threadIdx.x & 31;
    float4 xv = ((const float4*)g_x1)[(size_t)n * 32 + lane];
    float4 wv = ((const float4*)fcw)[lane];
    float d = xv.x * wv.x + xv.y * wv.y + xv.z * wv.z + xv.w * wv.w;
#pragma unroll
    for (int o = 16; o; o >>= 1) d += __shfl_xor_sync(0xffffffffu, d, o);
    if (lane == 0) atomicAdd(&g_acc[g_batch[n]], d);
}

__global__ void final_kernel(float* __restrict__ out, const float* __restrict__ fcb) {
    int g = blockIdx.x * blockDim.x + threadIdx.x;
    if (g < GG) out[g] = g_acc[g] / fmaxf(g_cnt[g], 1.f) + fcb[0];
}

// ---------------- launch ----------------
extern "C" void kernel_launch(void* const* d_in, const int* in_sizes, int n_in,
                              void* d_out, int out_size) {
    const float* x     = (const float*)d_in[0];
    const void*  ei    = d_in[1];
    const void*  batch = d_in[2];
    const float* Wl[3] = {(const float*)d_in[3], (const float*)d_in[6], (const float*)d_in[9]};
    const float* bb[3] = {(const float*)d_in[4], (const float*)d_in[7], (const float*)d_in[10]};
    const float* Wr[3] = {(const float*)d_in[5], (const float*)d_in[8], (const float*)d_in[11]};
    const float* fcw = (const float*)d_in[12];
    const float* fcb = (const float*)d_in[13];
    float* out = (float*)d_out;

    // prep: dtype probe, histogram, CSR build
    detect_dtype_kernel<<<1, 1>>>(ei);
    zero_small_kernel<<<NB, 256>>>();
    convert_edges_kernel<<<4096, 256>>>(ei);
    convert_batch_kernel<<<NB, 256>>>(batch);
    scan_part1_kernel<<<NB, 256>>>();
    scan_part2_kernel<<<1, 256>>>();
    scan_part3_kernel<<<NB, 256>>>();
    place_edges_kernel<<<4096, 256>>>();

    const int gather_blocks  = (NN * 32 + 255) / 256;
    const int combine_blocks = (NN + 127) / 128;

    // layer 0: x -> g_x1
    gather_kernel<<<gather_blocks, 256>>>(x, 0);
    combine_kernel<<<combine_blocks, 256>>>(x, 0, 1, Wl[0], bb[0], Wr[0]);
    // layer 1: g_x1 -> g_x2
    gather_kernel<<<gather_blocks, 256>>>(x, 1);
    combine_kernel<<<combine_blocks, 256>>>(x, 1, 2, Wl[1], bb[1], Wr[1]);
    // layer 2: g_x2 -> g_x1
    gather_kernel<<<gather_blocks, 256>>>(x, 2);
    combine_kernel<<<combine_blocks, 256>>>(x, 2, 1, Wl[2], bb[2], Wr[2]);

    // pool + fc
    pool_kernel<<<(NN * 32 + 255) / 256, 256>>>(fcw);
    final_kernel<<<(GG + 255) / 256, 256>>>(out, fcb);
}

// round 4
// speedup vs baseline: 2.2152x; 1.3162x over previous
#include <cuda_runtime.h>
#include <cuda_bf16.h>

#define NN 50000
#define EE 1600000
#define DD 128
#define GG 512
#define NB 196          // ceil(NN/256)
#define CBLK 391        // ceil(NN/128)

// ---------------- scratch (static device globals; no allocation) ----------------
__device__ __nv_bfloat16 g_A_hi[NN * 256];   // [agg | x] hi part, bf16
__device__ __nv_bfloat16 g_A_lo[NN * 256];   // [agg | x] lo residual, bf16
__device__ __nv_bfloat16 g_Bh[3 * 128 * 256];// per-layer [Wl|Wr] hi, row n, col k
__device__ __nv_bfloat16 g_Bl[3 * 128 * 256];// per-layer lo
__device__ float g_x1[NN * DD];      // layer output ping (fp32, for gather/pool)
__device__ float g_x2[NN * DD];      // layer output pong
__device__ float g_invdeg[NN];
__device__ int   g_deg[NN];
__device__ int   g_rowptr[NN];
__device__ int   g_cursor[NN];
__device__ int   g_src[EE];
__device__ int   g_dst[EE];
__device__ int   g_esrc[EE];
__device__ int   g_batch[NN];
__device__ float g_acc[GG];
__device__ float g_cnt[GG];
__device__ int   g_blocksum[NB];
__device__ int   g_blockoff[NB];
__device__ int   g_is64;

// ---------------- dtype probe ----------------
__global__ void detect_dtype_kernel(const void* __restrict__ ei) {
    const long long* p = (const long long*)ei;
    int ok = 1;
#pragma unroll 1
    for (int i = 0; i < 64; i++) {
        long long v = p[i];
        if (v < 0 || v >= NN) ok = 0;
    }
    g_is64 = ok;
}

// ---------------- init / conversion ----------------
__global__ void zero_small_kernel() {
    int i = blockIdx.x * blockDim.x + threadIdx.x;
    if (i < NN) g_deg[i] = 0;
    if (i < GG) { g_acc[i] = 0.f; g_cnt[i] = 0.f; }
}

__global__ void convert_edges_kernel(const void* __restrict__ ei) {
    const int is64 = g_is64;
    const long long* p64 = (const long long*)ei;
    const int*       p32 = (const int*)ei;
    for (int i = blockIdx.x * blockDim.x + threadIdx.x; i < EE; i += gridDim.x * blockDim.x) {
        int s, d;
        if (is64) { s = (int)p64[i]; d = (int)p64[EE + i]; }
        else      { s = p32[i];      d = p32[EE + i]; }
        g_src[i] = s;
        g_dst[i] = d;
        atomicAdd(&g_deg[d], 1);
    }
}

__global__ void convert_batch_kernel(const void* __restrict__ b) {
    const int is64 = g_is64;
    const long long* p64 = (const long long*)b;
    const int*       p32 = (const int*)b;
    for (int i = blockIdx.x * blockDim.x + threadIdx.x; i < NN; i += gridDim.x * blockDim.x) {
        int g = is64 ? (int)p64[i] : p32[i];
        g_batch[i] = g;
        atomicAdd(&g_cnt[g], 1.f);
    }
}

// x (external fp32) -> A cols 128..255 hi/lo
__global__ void convert_x_kernel(const float* __restrict__ x) {
    for (int i = blockIdx.x * blockDim.x + threadIdx.x; i < NN * DD; i += gridDim.x * blockDim.x) {
        int row = i >> 7, col = i & 127;
        float v = x[i];
        __nv_bfloat16 h = __float2bfloat16(v);
        __nv_bfloat16 l = __float2bfloat16(v - __bfloat162float(h));
        g_A_hi[row * 256 + 128 + col] = h;
        g_A_lo[row * 256 + 128 + col] = l;
    }
}

// weights: layer l, B[n][k] = k<128 ? Wl[n][k] : Wr[n][k-128], hi/lo
__global__ void convert_w_kernel(const float* __restrict__ Wl, const float* __restrict__ Wr, int l) {
    int i = blockIdx.x * blockDim.x + threadIdx.x;   // 0 .. 128*256-1
    if (i >= 128 * 256) return;
    int n = i >> 8, k = i & 255;
    float v = (k < 128) ? Wl[n * 128 + k] : Wr[n * 128 + (k - 128)];
    __nv_bfloat16 h = __float2bfloat16(v);
    __nv_bfloat16 lo = __float2bfloat16(v - __bfloat162float(h));
    g_Bh[l * 128 * 256 + i] = h;
    g_Bl[l * 128 * 256 + i] = lo;
}

// ---------------- scan for CSR ----------------
__global__ void scan_part1_kernel() {
    __shared__ int sh[256];
    int i = blockIdx.x * 256 + threadIdx.x;
    int v = (i < NN) ? g_deg[i] : 0;
    sh[threadIdx.x] = v;
    __syncthreads();
    for (int o = 128; o; o >>= 1) {
        if (threadIdx.x < o) sh[threadIdx.x] += sh[threadIdx.x + o];
        __syncthreads();
    }
    if (threadIdx.x == 0) g_blocksum[blockIdx.x] = sh[0];
}

__global__ void scan_part2_kernel() {
    __shared__ int sh[256];
    int t = threadIdx.x;
    sh[t] = (t < NB) ? g_blocksum[t] : 0;
    __syncthreads();
    for (int o = 1; o < 256; o <<= 1) {
        int v = (t >= o) ? sh[t - o] : 0;
        __syncthreads();
        sh[t] += v;
        __syncthreads();
    }
    if (t < NB) g_blockoff[t] = (t == 0) ? 0 : sh[t - 1];
}

__global__ void scan_part3_kernel() {
    __shared__ int sh[256];
    int t = threadIdx.x;
    int i = blockIdx.x * 256 + t;
    int v = (i < NN) ? g_deg[i] : 0;
    sh[t] = v;
    __syncthreads();
    for (int o = 1; o < 256; o <<= 1) {
        int u = (t >= o) ? sh[t - o] : 0;
        __syncthreads();
        sh[t] += u;
        __syncthreads();
    }
    if (i < NN) {
        int excl = sh[t] - v + g_blockoff[blockIdx.x];
        g_rowptr[i] = excl;
        g_cursor[i] = excl;
        g_invdeg[i] = 1.f / fmaxf((float)v, 1.f);
    }
}

__global__ void place_edges_kernel() {
    for (int i = blockIdx.x * blockDim.x + threadIdx.x; i < EE; i += gridDim.x * blockDim.x) {
        int d = g_dst[i];
        int pos = atomicAdd(&g_cursor[d], 1);
        g_esrc[pos] = g_src[i];
    }
}

// ---------------- gather mean -> A cols 0..127 (hi/lo bf16) ----------------
// xsel: 0 = external x, 1 = g_x1, 2 = g_x2
__global__ __launch_bounds__(256) void gather_kernel(const float* __restrict__ xext, int xsel) {
    const float* __restrict__ xin = (xsel == 0) ? xext : (xsel == 1 ? g_x1 : g_x2);
    int warp = (blockIdx.x * 256 + threadIdx.x) >> 5;
    if (warp >= NN) return;
    int lane = threadIdx.x & 31;
    int beg = g_rowptr[warp];
    int end = beg + g_deg[warp];

    float4 acc = make_float4(0.f, 0.f, 0.f, 0.f);
    int e = beg;
#pragma unroll 1
    for (; e + 4 <= end; e += 4) {
        int s0 = g_esrc[e + 0];
        int s1 = g_esrc[e + 1];
        int s2 = g_esrc[e + 2];
        int s3 = g_esrc[e + 3];
        float4 v0 = __ldg((const float4*)xin + (size_t)s0 * 32 + lane);
        float4 v1 = __ldg((const float4*)xin + (size_t)s1 * 32 + lane);
        float4 v2 = __ldg((const float4*)xin + (size_t)s2 * 32 + lane);
        float4 v3 = __ldg((const float4*)xin + (size_t)s3 * 32 + lane);
        acc.x += v0.x + v1.x + v2.x + v3.x;
        acc.y += v0.y + v1.y + v2.y + v3.y;
        acc.z += v0.z + v1.z + v2.z + v3.z;
        acc.w += v0.w + v1.w + v2.w + v3.w;
    }
#pragma unroll 1
    for (; e < end; e++) {
        int s = g_esrc[e];
        float4 v = __ldg((const float4*)xin + (size_t)s * 32 + lane);
        acc.x += v.x; acc.y += v.y; acc.z += v.z; acc.w += v.w;
    }
    float inv = g_invdeg[warp];
    float a[4] = {acc.x * inv, acc.y * inv, acc.z * inv, acc.w * inv};
    unsigned int hp[2], lp[2];
#pragma unroll
    for (int p = 0; p < 2; p++) {
        __nv_bfloat16 h0 = __float2bfloat16(a[p * 2 + 0]);
        __nv_bfloat16 h1 = __float2bfloat16(a[p * 2 + 1]);
        __nv_bfloat16 l0 = __float2bfloat16(a[p * 2 + 0] - __bfloat162float(h0));
        __nv_bfloat16 l1 = __float2bfloat16(a[p * 2 + 1] - __bfloat162float(h1));
        hp[p] = (unsigned int)__bfloat16_as_ushort(h0) | ((unsigned int)__bfloat16_as_ushort(h1) << 16);
        lp[p] = (unsigned int)__bfloat16_as_ushort(l0) | ((unsigned int)__bfloat16_as_ushort(l1) << 16);
    }
    size_t off = (size_t)warp * 256 + lane * 4;
    *(uint2*)&g_A_hi[off] = make_uint2(hp[0], hp[1]);
    *(uint2*)&g_A_lo[off] = make_uint2(lp[0], lp[1]);
}

// ---------------- combine via mma.sync bf16 split: Y = relu(A @ B^T + b) ----------------
// A[128 rows][256] hi/lo bf16, B[128 n][256 k] hi/lo bf16. acc = AhBh + AhBl + AlBh.
// Block 256 thr = 8 warps (4 along M x 2 along N), warp tile 32x64. K chunks of 32.
#define MMA16816(d, a, b0_, b1_) \
    asm volatile("mma.sync.aligned.m16n8k16.row.col.f32.bf16.bf16.f32 " \
                 "{%0,%1,%2,%3},{%4,%5,%6,%7},{%8,%9},{%0,%1,%2,%3};" \
                 : "+f"(d[0]), "+f"(d[1]), "+f"(d[2]), "+f"(d[3]) \
                 : "r"(a[0]), "r"(a[1]), "r"(a[2]), "r"(a[3]), "r"(b0_), "r"(b1_))

__global__ __launch_bounds__(256, 2) void combine_kernel(
    int layer, const float* __restrict__ bias, int osel)
{
    float* __restrict__ y = (osel == 1) ? g_x1 : g_x2;
    const __nv_bfloat16* __restrict__ Bh = g_Bh + layer * 128 * 256;
    const __nv_bfloat16* __restrict__ Bl = g_Bl + layer * 128 * 256;

    __shared__ __nv_bfloat16 sAh[128 * 36];
    __shared__ __nv_bfloat16 sAl[128 * 36];
    __shared__ __nv_bfloat16 sBh[128 * 36];
    __shared__ __nv_bfloat16 sBl[128 * 36];

    const int tid = threadIdx.x;
    const int lane = tid & 31;
    const int warp = tid >> 5;
    const int wm = warp & 3;        // 0..3 -> M offset wm*32
    const int wn = warp >> 2;       // 0..1 -> N offset wn*64
    const int row0 = blockIdx.x * 128;
    const int gr = lane >> 2;       // group row 0..7
    const int tg2 = (lane & 3) * 2; // 0,2,4,6

    float acc[2][8][4];
#pragma unroll
    for (int mt = 0; mt < 2; mt++)
#pragma unroll
        for (int nt = 0; nt < 8; nt++)
#pragma unroll
            for (int q = 0; q < 4; q++) acc[mt][nt][q] = 0.f;

#pragma unroll 1
    for (int c = 0; c < 8; c++) {
        const int k0 = c * 32;
        // load tiles: 128 rows x 32 cols bf16 each; 8B per thread-iter
#pragma unroll
        for (int it = 0; it < 4; it++) {
            int s = tid + it * 256;         // 0..1023
            int r = s >> 3;
            int c4 = (s & 7) * 4;
            int grow = row0 + r; if (grow >= NN) grow = NN - 1;
            *(uint2*)&sAh[r * 36 + c4] = *(const uint2*)&g_A_hi[(size_t)grow * 256 + k0 + c4];
            *(uint2*)&sAl[r * 36 + c4] = *(const uint2*)&g_A_lo[(size_t)grow * 256 + k0 + c4];
            *(uint2*)&sBh[r * 36 + c4] = *(const uint2*)&Bh[r * 256 + k0 + c4];
            *(uint2*)&sBl[r * 36 + c4] = *(const uint2*)&Bl[r * 256 + k0 + c4];
        }
        __syncthreads();

#pragma unroll
        for (int kk = 0; kk < 32; kk += 16) {
            unsigned int ah[2][4], al[2][4];
#pragma unroll
            for (int mt = 0; mt < 2; mt++) {
                int rb = wm * 32 + mt * 16;
                ah[mt][0] = *(const unsigned int*)&sAh[(rb + gr) * 36 + kk + tg2];
                ah[mt][1] = *(const unsigned int*)&sAh[(rb + gr + 8) * 36 + kk + tg2];
                ah[mt][2] = *(const unsigned int*)&sAh[(rb + gr) * 36 + kk + tg2 + 8];
                ah[mt][3] = *(const unsigned int*)&sAh[(rb + gr + 8) * 36 + kk + tg2 + 8];
                al[mt][0] = *(const unsigned int*)&sAl[(rb + gr) * 36 + kk + tg2];
                al[mt][1] = *(const unsigned int*)&sAl[(rb + gr + 8) * 36 + kk + tg2];
                al[mt][2] = *(const unsigned int*)&sAl[(rb + gr) * 36 + kk + tg2 + 8];
                al[mt][3] = *(const unsigned int*)&sAl[(rb + gr + 8) * 36 + kk + tg2 + 8];
            }
#pragma unroll
            for (int nt = 0; nt < 8; nt++) {
                int nb = wn * 64 + nt * 8 + gr;
                unsigned int bh0 = *(const unsigned int*)&sBh[nb * 36 + kk + tg2];
                unsigned int bh1 = *(const unsigned int*)&sBh[nb * 36 + kk + tg2 + 8];
                unsigned int bl0 = *(const unsigned int*)&sBl[nb * 36 + kk + tg2];
                unsigned int bl1 = *(const unsigned int*)&sBl[nb * 36 + kk + tg2 + 8];
#pragma unroll
                for (int mt = 0; mt < 2; mt++) {
                    MMA16816(acc[mt][nt], ah[mt], bh0, bh1);
                    MMA16816(acc[mt][nt], ah[mt], bl0, bl1);
                    MMA16816(acc[mt][nt], al[mt], bh0, bh1);
                }
            }
        }
        __syncthreads();
    }

    // epilogue: bias + relu; write y fp32 and A x-part (cols 128..255) hi/lo
#pragma unroll
    for (int mt = 0; mt < 2; mt++) {
#pragma unroll
        for (int nt = 0; nt < 8; nt++) {
            int col = wn * 64 + nt * 8 + tg2;
            float b0 = bias[col], b1 = bias[col + 1];
#pragma unroll
            for (int half = 0; half < 2; half++) {
                int row = row0 + wm * 32 + mt * 16 + gr + half * 8;
                if (row >= NN) continue;
                float v0 = fmaxf(acc[mt][nt][half * 2 + 0] + b0, 0.f);
                float v1 = fmaxf(acc[mt][nt][half * 2 + 1] + b1, 0.f);
                *(float2*)&y[(size_t)row * DD + col] = make_float2(v0, v1);
                __nv_bfloat16 h0 = __float2bfloat16(v0);
                __nv_bfloat16 h1 = __float2bfloat16(v1);
                __nv_bfloat16 l0 = __float2bfloat16(v0 - __bfloat162float(h0));
                __nv_bfloat16 l1 = __float2bfloat16(v1 - __bfloat162float(h1));
                unsigned int hp = (unsigned int)__bfloat16_as_ushort(h0) | ((unsigned int)__bfloat16_as_ushort(h1) << 16);
                unsigned int lp = (unsigned int)__bfloat16_as_ushort(l0) | ((unsigned int)__bfloat16_as_ushort(l1) << 16);
                *(unsigned int*)&g_A_hi[(size_t)row * 256 + 128 + col] = hp;
                *(unsigned int*)&g_A_lo[(size_t)row * 256 + 128 + col] = lp;
            }
        }
    }
}

// ---------------- pooling ----------------
__global__ void pool_kernel(const float* __restrict__ fcw) {
    long long t = (long long)blockIdx.x * blockDim.x + threadIdx.x;
    int n = (int)(t >> 5);
    if (n >= NN) return;
    int lane = threadIdx.x & 31;
    float4 xv = ((const float4*)g_x1)[(size_t)n * 32 + lane];
    float4 wv = ((const float4*)fcw)[lane];
    float d = xv.x * wv.x + xv.y * wv.y + xv.z * wv.z + xv.w * wv.w;
#pragma unroll
    for (int o = 16; o; o >>= 1) d += __shfl_xor_sync(0xffffffffu, d, o);
    if (lane == 0) atomicAdd(&g_acc[g_batch[n]], d);
}

__global__ void final_kernel(float* __restrict__ out, const float* __restrict__ fcb) {
    int g = blockIdx.x * blockDim.x + threadIdx.x;
    if (g < GG) out[g] = g_acc[g] / fmaxf(g_cnt[g], 1.f) + fcb[0];
}

// ---------------- launch ----------------
extern "C" void kernel_launch(void* const* d_in, const int* in_sizes, int n_in,
                              void* d_out, int out_size) {
    const float* x     = (const float*)d_in[0];
    const void*  ei    = d_in[1];
    const void*  batch = d_in[2];
    const float* Wl[3] = {(const float*)d_in[3], (const float*)d_in[6], (const float*)d_in[9]};
    const float* bb[3] = {(const float*)d_in[4], (const float*)d_in[7], (const float*)d_in[10]};
    const float* Wr[3] = {(const float*)d_in[5], (const float*)d_in[8], (const float*)d_in[11]};
    const float* fcw = (const float*)d_in[12];
    const float* fcb = (const float*)d_in[13];
    float* out = (float*)d_out;

    // prep
    detect_dtype_kernel<<<1, 1>>>(ei);
    zero_small_kernel<<<NB, 256>>>();
    convert_edges_kernel<<<4096, 256>>>(ei);
    convert_batch_kernel<<<NB, 256>>>(batch);
    convert_x_kernel<<<2048, 256>>>(x);
    for (int l = 0; l < 3; l++)
        convert_w_kernel<<<128, 256>>>(Wl[l], Wr[l], l);
    scan_part1_kernel<<<NB, 256>>>();
    scan_part2_kernel<<<1, 256>>>();
    scan_part3_kernel<<<NB, 256>>>();
    place_edges_kernel<<<4096, 256>>>();

    const int gather_blocks = (NN * 32 + 255) / 256;

    // layer 0: x -> g_x1
    gather_kernel<<<gather_blocks, 256>>>(x, 0);
    combine_kernel<<<CBLK, 256>>>(0, bb[0], 1);
    // layer 1: g_x1 -> g_x2
    gather_kernel<<<gather_blocks, 256>>>(x, 1);
    combine_kernel<<<CBLK, 256>>>(1, bb[1], 2);
    // layer 2: g_x2 -> g_x1
    gather_kernel<<<gather_blocks, 256>>>(x, 2);
    combine_kernel<<<CBLK, 256>>>(2, bb[2], 1);

    // pool + fc
    pool_kernel<<<(NN * 32 + 255) / 256, 256>>>(fcw);
    final_kernel<<<(GG + 255) / 256, 256>>>(out, fcb);
}